// round 6
// baseline (speedup 1.0000x reference)
#include <cuda_runtime.h>
#include <cuda_bf16.h>
#include <math.h>
#include <string.h>

#define NROWS   65536
#define DIM     64
#define KC      512
#define NQ      (NROWS*DIM)
#define GRID    148
#define THREADS 256
#define WARPS   8
#define WTILES  (NROWS/32)       // 2048 warp-tiles of 32 rows
#define WSTRIDE (GRID*WARPS)     // 1184
#define DELTA   4e-3f
#define CAND_MAX 16

// smem byte offsets
#define SMO_SB    0
#define SMO_CODES 2048                    // 512 x 36 u32 (bf16 pairs, stride-36 words)
#define SMO_XBF   (SMO_CODES + 73728)     // 75776: 8 warps x 32 rows x 36 u32
#define SMO_SC    (SMO_XBF + 36864)       // 112640: 8 warps x 32 rows x 68 f32
#define SMO_CAND  (SMO_SC + 69632)        // 182272: 256 lanes x 16 float2
#define SMEM_TOTAL (SMO_CAND + 32768)     // 215040

// Output: [0] loss | [1..NQ] quantized_st (base out+1) | [1+NQ] perplexity | [2+NQ..] indices

__device__ unsigned     g_codes[KC*36];
__device__ float        g_sb[KC];
__device__ int          g_hist[KC];
__device__ double       g_sse;
__device__ unsigned int g_done;

__device__ __forceinline__ unsigned pack_bf2(float lo, float hi) {
    __nv_bfloat162 p = __floats2bfloat162_rn(lo, hi);  // .x (lo) -> low 16 bits
    unsigned u; memcpy(&u, &p, 4);
    return u;
}

// ---- prep: bf16 code image (stride 36 words), exact norms, zero globals -----
__global__ void prep_kernel(const float* __restrict__ emb) {
    int k = blockIdx.x * blockDim.x + threadIdx.x;
    if (k >= KC) return;
    if (k == 0) { g_sse = 0.0; g_done = 0u; }
    g_hist[k] = 0;

    const float* e = emb + k * DIM;
    float b0 = 0.f, b1 = 0.f;
    #pragma unroll
    for (int i = 0; i < DIM; i += 2) {
        b0 = fmaf(e[i],     e[i],     b0);
        b1 = fmaf(e[i + 1], e[i + 1], b1);
    }
    g_sb[k] = b0 + b1;

    #pragma unroll
    for (int i = 0; i < 32; i++)
        g_codes[k * 36 + i] = pack_bf2(e[2 * i], e[2 * i + 1]);
    #pragma unroll
    for (int i = 32; i < 36; i++) g_codes[k * 36 + i] = 0u;
}

// ---- warp-level bf16 MMA (base ISA, compiles for compute_103) ---------------
__device__ __forceinline__ void mma_bf16(float* d, const unsigned* a,
                                         unsigned b0, unsigned b1) {
    asm volatile(
        "mma.sync.aligned.m16n8k16.row.col.f32.bf16.bf16.f32 "
        "{%0,%1,%2,%3}, {%4,%5,%6,%7}, {%8,%9}, {%0,%1,%2,%3};"
        : "+f"(d[0]), "+f"(d[1]), "+f"(d[2]), "+f"(d[3])
        : "r"(a[0]), "r"(a[1]), "r"(a[2]), "r"(a[3]), "r"(b0), "r"(b1));
}

// -----------------------------------------------------------------------------
__global__ void __launch_bounds__(THREADS, 1)
vq_mma_kernel(const float* __restrict__ inp,
              const float* __restrict__ emb,
              float* __restrict__ out)
{
    extern __shared__ char sm[];
    float*    sb    = reinterpret_cast<float*>(sm + SMO_SB);
    unsigned* codes = reinterpret_cast<unsigned*>(sm + SMO_CODES);
    unsigned* xbf   = reinterpret_cast<unsigned*>(sm + SMO_XBF);
    float*    scb   = reinterpret_cast<float*>(sm + SMO_SC);
    float2*   cand  = reinterpret_cast<float2*>(sm + SMO_CAND);

    const int tid  = threadIdx.x;
    const int wid  = tid >> 5, lane = tid & 31;
    const int g    = lane >> 2, tg = lane & 3;   // mma groupID / thread-in-group

    for (int i = tid; i < KC * 36 / 4; i += THREADS)
        reinterpret_cast<uint4*>(codes)[i] =
            reinterpret_cast<const uint4*>(g_codes)[i];
    for (int i = tid; i < KC; i += THREADS) sb[i] = g_sb[i];
    __syncthreads();

    unsigned* xw = xbf + wid * 32 * 36;          // warp-private bf16 x tile
    float*    sc = scb + wid * 32 * 68;          // warp-private score buffer
    float2*   cl = cand + (size_t)tid * CAND_MAX;

    for (int wt = blockIdx.x * WARPS + wid; wt < WTILES; wt += WSTRIDE) {
        const int row = wt * 32 + lane;

        // ---- load x (fp32, kept in regs), A = sum(x^2), convert -> bf16 ----
        float4 x4[16];
        {
            const float4* xp = reinterpret_cast<const float4*>(inp + (size_t)row * DIM);
            #pragma unroll
            for (int i = 0; i < 16; i++) x4[i] = xp[i];
        }
        float a0 = 0.f, a1 = 0.f;
        #pragma unroll
        for (int i = 0; i < 16; i++) {
            a0 = fmaf(x4[i].x, x4[i].x, a0);
            a1 = fmaf(x4[i].y, x4[i].y, a1);
            a0 = fmaf(x4[i].z, x4[i].z, a0);
            a1 = fmaf(x4[i].w, x4[i].w, a1);
        }
        const float A = a0 + a1;

        #pragma unroll
        for (int i = 0; i < 16; i++) {
            xw[lane * 36 + 2 * i]     = pack_bf2(x4[i].x, x4[i].y);
            xw[lane * 36 + 2 * i + 1] = pack_bf2(x4[i].z, x4[i].w);
        }
        __syncwarp();

        float m     = -3.402823466e+38f;
        float bestd =  3.402823466e+38f;
        int   bik   = 0;
        int   nc    = 0;

        // exact fp32 recheck, JAX-replicating (tie -> lower k)
        auto recheck = [&](int k) {
            const float4* ep = reinterpret_cast<const float4*>(emb + (size_t)k * DIM);
            float c0 = 0.f, c1 = 0.f;
            #pragma unroll
            for (int i = 0; i < 16; i++) {
                float4 ev = ep[i];
                c0 = fmaf(x4[i].x, ev.x, c0);
                c1 = fmaf(x4[i].y, ev.y, c1);
                c0 = fmaf(x4[i].z, ev.z, c0);
                c1 = fmaf(x4[i].w, ev.w, c1);
            }
            float c  = c0 + c1;
            float t  = A + sb[k];          // fl(A + b_k)
            float dd = t - 2.0f * c;       // fl(t - 2c)
            if (dd < bestd || (dd == bestd && k < bik)) { bestd = dd; bik = k; }
        };

        for (int ch = 0; ch < 8; ch++) {
            float acc[2][8][4];
            #pragma unroll
            for (int mt = 0; mt < 2; mt++)
                #pragma unroll
                for (int nt = 0; nt < 8; nt++)
                    #pragma unroll
                    for (int e = 0; e < 4; e++) acc[mt][nt][e] = 0.f;

            #pragma unroll
            for (int ks = 0; ks < 4; ks++) {
                unsigned af[2][4];
                #pragma unroll
                for (int mt = 0; mt < 2; mt++) {
                    int r0 = mt * 16 + g;
                    af[mt][0] = xw[r0 * 36       + ks * 8 + tg];
                    af[mt][1] = xw[(r0 + 8) * 36 + ks * 8 + tg];
                    af[mt][2] = xw[r0 * 36       + ks * 8 + tg + 4];
                    af[mt][3] = xw[(r0 + 8) * 36 + ks * 8 + tg + 4];
                }
                #pragma unroll
                for (int nt = 0; nt < 8; nt++) {
                    int col = ch * 64 + nt * 8 + g;
                    unsigned b0 = codes[col * 36 + ks * 8 + tg];
                    unsigned b1 = codes[col * 36 + ks * 8 + tg + 4];
                    mma_bf16(acc[0][nt], af[0], b0, b1);
                    mma_bf16(acc[1][nt], af[1], b0, b1);
                }
            }

            // dump scores: rows g,(g+8) (+16 for mt1), cols nt*8 + 2tg (+1)
            #pragma unroll
            for (int mt = 0; mt < 2; mt++)
                #pragma unroll
                for (int nt = 0; nt < 8; nt++) {
                    int r0 = mt * 16 + g, c0 = nt * 8 + 2 * tg;
                    *reinterpret_cast<float2*>(&sc[r0 * 68 + c0]) =
                        make_float2(acc[mt][nt][0], acc[mt][nt][1]);
                    *reinterpret_cast<float2*>(&sc[(r0 + 8) * 68 + c0]) =
                        make_float2(acc[mt][nt][2], acc[mt][nt][3]);
                }
            __syncwarp();

            // scan own row (lane L -> row L), conflict-free float4 reads
            #pragma unroll 4
            for (int J = 0; J < 16; J++) {
                float4 s4 = *reinterpret_cast<float4*>(&sc[lane * 68 + 4 * J]);
                #pragma unroll
                for (int e = 0; e < 4; e++) {
                    int   k  = ch * 64 + 4 * J + e;
                    float cv = (e == 0) ? s4.x : (e == 1) ? s4.y : (e == 2) ? s4.z : s4.w;
                    float s  = fmaf(-0.5f, sb[k], cv);
                    if (s >= m - DELTA) {                 // rare (~8/row)
                        if (s > m) m = s;
                        if (nc < CAND_MAX)
                            cl[nc++] = make_float2(s, __int_as_float(k));
                        else
                            recheck(k);                   // overflow fallback
                    }
                }
            }
            __syncwarp();
        }

        // filter deferred candidates by final max, exact recheck survivors
        const float thr = m - DELTA;
        for (int i = 0; i < nc; i++) {
            float2 p = cl[i];
            if (p.x >= thr) recheck(__float_as_int(p.y));
        }

        // ---- epilogue: index, hist, quantized_st, SSE -----------------------
        out[2 + NQ + row] = (float)bik;
        atomicAdd(&g_hist[bik], 1);

        float* q = out + 1 + (size_t)row * DIM;   // base == 1 mod 4 floats
        const float4* ep = reinterpret_cast<const float4*>(emb + (size_t)bik * DIM);
        float qs[DIM];
        float sse = 0.f;
        #pragma unroll
        for (int i = 0; i < 16; i++) {
            float4 ev = ep[i];
            float d0 = ev.x - x4[i].x, d1 = ev.y - x4[i].y;
            float d2 = ev.z - x4[i].z, d3 = ev.w - x4[i].w;
            qs[4*i]   = x4[i].x + d0;             // fl(x + fl(q-x)) exactly
            qs[4*i+1] = x4[i].y + d1;
            qs[4*i+2] = x4[i].z + d2;
            qs[4*i+3] = x4[i].w + d3;
            sse += d0*d0 + d1*d1 + d2*d2 + d3*d3;
        }
        q[0] = qs[0]; q[1] = qs[1]; q[2] = qs[2];
        float4* q4 = reinterpret_cast<float4*>(q + 3);
        #pragma unroll
        for (int i = 0; i < 15; i++)
            q4[i] = make_float4(qs[3+4*i], qs[4+4*i], qs[5+4*i], qs[6+4*i]);
        q[63] = qs[63];

        float wsum = sse;
        #pragma unroll
        for (int off = 16; off > 0; off >>= 1)
            wsum += __shfl_xor_sync(0xFFFFFFFFu, wsum, off);
        if (lane == 0) atomicAdd(&g_sse, (double)wsum);
    }

    // ---- last CTA finalizes loss & perplexity -------------------------------
    __threadfence();
    __syncthreads();
    __shared__ unsigned s_last;
    if (tid == 0)
        s_last = (atomicAdd(&g_done, 1u) == GRID - 1u) ? 1u : 0u;
    __syncthreads();
    if (s_last) {
        __threadfence();
        __shared__ float red[THREADS];
        float acc = 0.f;
        for (int b = tid; b < KC; b += THREADS) {
            float pb = (float)g_hist[b] * (1.0f / (float)NROWS);
            acc += pb * logf(pb + 1e-10f);
        }
        red[tid] = acc;
        __syncthreads();
        for (int off = THREADS / 2; off > 0; off >>= 1) {
            if (tid < off) red[tid] += red[tid + off];
            __syncthreads();
        }
        if (tid == 0) {
            out[0]      = (float)(1.25 * (g_sse * (1.0 / (double)NQ)));
            out[1 + NQ] = expf(-red[0]);
        }
    }
}

extern "C" void kernel_launch(void* const* d_in, const int* in_sizes, int n_in,
                              void* d_out, int out_size)
{
    const float* inp = (const float*)d_in[0];
    const float* emb = (const float*)d_in[1];
    if (n_in >= 2 && in_sizes[0] == KC * DIM) {
        const float* t = inp; inp = emb; emb = t;
    }
    float* out = (float*)d_out;

    cudaFuncSetAttribute(vq_mma_kernel,
                         cudaFuncAttributeMaxDynamicSharedMemorySize, SMEM_TOTAL);

    prep_kernel<<<4, 128>>>(emb);
    vq_mma_kernel<<<GRID, THREADS, SMEM_TOTAL>>>(inp, emb, out);
}